// round 1
// baseline (speedup 1.0000x reference)
#include <cuda_runtime.h>
#include <math.h>

#define WSZ      8
#define NH       8
#define CDIM     192
#define HD       24
#define NTOK     64
#define HIMG     256
#define WIMG     256
#define NWIN_TOT 4096

// smem strides (floats), padded for bank-conflict-free float4 access
#define XS_STRIDE  196   // 196 % 32 == 4
#define QKV_STRIDE 580   // 580 % 32 == 4
#define WP_STRIDE  68    // 68  % 32 == 4
#define KHALF      96    // K staged in 2 halves of 96

__device__ float g_bias[NH * NTOK * NTOK];   // 128 KB, L2-resident

// ---------------------------------------------------------------------------
// Kernel A: relative-position-bias table  (225,2) -> MLP(2->512->8) -> gather
// ---------------------------------------------------------------------------
__global__ void bias_kernel(const float* __restrict__ cpb_w1,
                            const float* __restrict__ cpb_b1,
                            const float* __restrict__ cpb_w2) {
    __shared__ float s_table[225 * NH];
    int t = threadIdx.x;
    if (t < 225) {
        int a = t / 15, b = t - a * 15;
        float t0 = (float)(a - 7) * (8.0f / 7.0f);
        float t1 = (float)(b - 7) * (8.0f / 7.0f);
        const float inv_l8 = 1.0f / 3.0f;                 // 1/log2(8)
        float r0 = copysignf(log2f(fabsf(t0) + 1.0f) * inv_l8, t0);
        float r1 = copysignf(log2f(fabsf(t1) + 1.0f) * inv_l8, t1);
        float acc[NH];
        #pragma unroll
        for (int h = 0; h < NH; h++) acc[h] = 0.f;
        for (int k = 0; k < 512; k++) {
            float hv = r0 * cpb_w1[k] + r1 * cpb_w1[512 + k] + cpb_b1[k];
            hv = fmaxf(hv, 0.f);
            #pragma unroll
            for (int h = 0; h < NH; h++) acc[h] += hv * cpb_w2[k * NH + h];
        }
        #pragma unroll
        for (int h = 0; h < NH; h++)
            s_table[t * NH + h] = 16.f / (1.f + expf(-acc[h]));
    }
    __syncthreads();
    for (int id = t; id < NH * NTOK * NTOK; id += blockDim.x) {
        int h = id >> 12;
        int i = (id >> 6) & 63;
        int j = id & 63;
        int di = (i >> 3) - (j >> 3) + 7;
        int dj = (i & 7)  - (j & 7)  + 7;
        g_bias[id] = s_table[(di * 15 + dj) * NH + h];
    }
}

// ---------------------------------------------------------------------------
// GEMM helpers: 64xP panel, K staged in smem (transposed, [k][col]), 4x4 tiles
// ---------------------------------------------------------------------------
__device__ __forceinline__ void load_wpT(float* wpT, const float* __restrict__ W,
                                         int cp, int kh, int t) {
    // wpT[k][c] = W[(cp+c)*CDIM + kh*KHALF + k]   (coalesced gmem reads)
    for (int idx = t; idx < 64 * KHALF; idx += 256) {
        int c = idx / KHALF;
        int k = idx - c * KHALF;
        wpT[k * WP_STRIDE + c] = W[(cp + c) * CDIM + kh * KHALF + k];
    }
}

__device__ __forceinline__ void gemm_accum(const float* __restrict__ a_base, int lda,
                                           const float* __restrict__ wpT, int c0,
                                           float acc[4][4]) {
    #pragma unroll 4
    for (int k4 = 0; k4 < KHALF; k4 += 4) {
        float4 b0 = *(const float4*)(wpT + (k4 + 0) * WP_STRIDE + c0);
        float4 b1 = *(const float4*)(wpT + (k4 + 1) * WP_STRIDE + c0);
        float4 b2 = *(const float4*)(wpT + (k4 + 2) * WP_STRIDE + c0);
        float4 b3 = *(const float4*)(wpT + (k4 + 3) * WP_STRIDE + c0);
        #pragma unroll
        for (int r = 0; r < 4; r++) {
            float4 a = *(const float4*)(a_base + r * lda + k4);
            acc[r][0] += a.x * b0.x + a.y * b1.x + a.z * b2.x + a.w * b3.x;
            acc[r][1] += a.x * b0.y + a.y * b1.y + a.z * b2.y + a.w * b3.y;
            acc[r][2] += a.x * b0.z + a.y * b1.z + a.z * b2.z + a.w * b3.z;
            acc[r][3] += a.x * b0.w + a.y * b1.w + a.z * b2.w + a.w * b3.w;
        }
    }
}

// ---------------------------------------------------------------------------
// Kernel B: fused window attention, one CTA per 8x8 window
// ---------------------------------------------------------------------------
__global__ void __launch_bounds__(256)
win_attn_kernel(const float* __restrict__ x,
                const float* __restrict__ qkv_w,
                const float* __restrict__ q_bias,
                const float* __restrict__ v_bias,
                const float* __restrict__ logit_scale,
                const float* __restrict__ proj_w,
                const float* __restrict__ proj_b,
                float* __restrict__ out) {
    extern __shared__ float smem[];
    float* xs  = smem;                         // [64][196]
    float* qkv = xs  + NTOK * XS_STRIDE;       // [64][580] (q|k|v cols 0..575)
    float* wpT = qkv + NTOK * QKV_STRIDE;      // [96][68] weight panel / norms
    __shared__ float s_scale[NH];

    const int t    = threadIdx.x;
    const int wi   = blockIdx.x;
    const int b    = wi >> 10;
    const int hblk = (wi >> 5) & 31;
    const int wblk = wi & 31;
    const int h0   = hblk * 8, w0 = wblk * 8;

    const float* xb = x + (size_t)b * CDIM * HIMG * WIMG;
    const size_t obase = (size_t)b * CDIM * HIMG * WIMG;

    // ---- gather window: xs[n][c] = x[b][c][h0+n/8][w0+n%8]
    for (int idx = t; idx < NTOK * CDIM; idx += 256) {
        int c = idx >> 6;
        int n = idx & 63;
        xs[n * XS_STRIDE + c] =
            xb[((size_t)c * HIMG + h0 + (n >> 3)) * WIMG + w0 + (n & 7)];
    }
    if (t < NH)
        s_scale[t] = expf(fminf(logit_scale[t], 4.60517018598809136804f)); // ln(100)
    __syncthreads();

    const int tx = t & 15, ty = t >> 4;
    const int c0 = tx * 4, r0 = ty * 4;

    // ================= QKV GEMM: qkv[64][576] = xs @ qkv_w^T + bias ========
    for (int p = 0; p < 9; p++) {
        const int cp = p * 64;
        float acc[4][4];
        #pragma unroll
        for (int r = 0; r < 4; r++)
            #pragma unroll
            for (int c = 0; c < 4; c++) acc[r][c] = 0.f;
        for (int kh = 0; kh < 2; kh++) {
            __syncthreads();                    // wpT free to overwrite
            load_wpT(wpT, qkv_w, cp, kh, t);
            __syncthreads();
            gemm_accum(xs + r0 * XS_STRIDE + kh * KHALF, XS_STRIDE, wpT, c0, acc);
        }
        #pragma unroll
        for (int c = 0; c < 4; c++) {
            int col = cp + c0 + c;
            float cb;
            if (col < CDIM)            cb = q_bias[col];
            else if (col < 2 * CDIM)   cb = 0.f;
            else                       cb = v_bias[col - 2 * CDIM];
            #pragma unroll
            for (int r = 0; r < 4; r++)
                qkv[(r0 + r) * QKV_STRIDE + col] = acc[r][c] + cb;
        }
    }
    __syncthreads();

    // ================= q/k row reciprocal norms ============================
    float* s_rq = wpT;         // [64][8]
    float* s_rk = wpT + 512;   // [64][8]
    for (int id = t; id < 1024; id += 256) {
        int qk = id >> 9;
        int n  = (id >> 3) & 63;
        int h  = id & 7;
        const float* p = qkv + n * QKV_STRIDE + qk * CDIM + h * HD;
        float s = 0.f;
        #pragma unroll
        for (int d4 = 0; d4 < 6; d4++) {
            float4 v = *(const float4*)(p + d4 * 4);
            s += v.x * v.x + v.y * v.y + v.z * v.z + v.w * v.w;
        }
        float r = 1.f / fmaxf(sqrtf(s), 1e-12f);
        (qk ? s_rk : s_rq)[n * 8 + h] = r;
    }
    __syncthreads();

    // ================= attention: per head, all in registers ================
    // thread t: row i = t>>2, covers keys j = sub + 4*jj (sub = t&3)
    {
        const int i   = t >> 2;
        const int sub = t & 3;
        const float* qrow = qkv + i * QKV_STRIDE;

        for (int h = 0; h < NH; h++) {
            const float* qh = qrow + h * HD;
            float4 q0 = *(const float4*)(qh + 0);
            float4 q1 = *(const float4*)(qh + 4);
            float4 q2 = *(const float4*)(qh + 8);
            float4 q3 = *(const float4*)(qh + 12);
            float4 q4 = *(const float4*)(qh + 16);
            float4 q5 = *(const float4*)(qh + 20);
            const float coef = s_rq[i * 8 + h] * s_scale[h];
            const float* bb  = g_bias + h * 4096 + i * 64;

            float e[16];
            float m = -1e30f;
            #pragma unroll
            for (int jj = 0; jj < 16; jj++) {
                int j = sub + 4 * jj;
                const float* kr = qkv + j * QKV_STRIDE + CDIM + h * HD;
                float4 k0 = *(const float4*)(kr + 0);
                float4 k1 = *(const float4*)(kr + 4);
                float4 k2 = *(const float4*)(kr + 8);
                float4 k3 = *(const float4*)(kr + 12);
                float4 k4 = *(const float4*)(kr + 16);
                float4 k5 = *(const float4*)(kr + 20);
                float dot = q0.x * k0.x + q0.y * k0.y + q0.z * k0.z + q0.w * k0.w
                          + q1.x * k1.x + q1.y * k1.y + q1.z * k1.z + q1.w * k1.w
                          + q2.x * k2.x + q2.y * k2.y + q2.z * k2.z + q2.w * k2.w
                          + q3.x * k3.x + q3.y * k3.y + q3.z * k3.z + q3.w * k3.w
                          + q4.x * k4.x + q4.y * k4.y + q4.z * k4.z + q4.w * k4.w
                          + q5.x * k5.x + q5.y * k5.y + q5.z * k5.z + q5.w * k5.w;
                float lg = dot * coef * s_rk[j * 8 + h] + __ldg(bb + j);
                e[jj] = lg;
                m = fmaxf(m, lg);
            }
            m = fmaxf(m, __shfl_xor_sync(0xffffffffu, m, 1));
            m = fmaxf(m, __shfl_xor_sync(0xffffffffu, m, 2));
            float sum = 0.f;
            #pragma unroll
            for (int jj = 0; jj < 16; jj++) {
                e[jj] = __expf(e[jj] - m);
                sum += e[jj];
            }
            sum += __shfl_xor_sync(0xffffffffu, sum, 1);
            sum += __shfl_xor_sync(0xffffffffu, sum, 2);
            const float rinv = 1.f / sum;

            float acc[HD];
            #pragma unroll
            for (int d = 0; d < HD; d++) acc[d] = 0.f;
            #pragma unroll
            for (int jj = 0; jj < 16; jj++) {
                int j = sub + 4 * jj;
                const float* vr = qkv + j * QKV_STRIDE + 2 * CDIM + h * HD;
                float ev = e[jj];
                #pragma unroll
                for (int d4 = 0; d4 < 6; d4++) {
                    float4 v = *(const float4*)(vr + d4 * 4);
                    acc[d4 * 4 + 0] += ev * v.x;
                    acc[d4 * 4 + 1] += ev * v.y;
                    acc[d4 * 4 + 2] += ev * v.z;
                    acc[d4 * 4 + 3] += ev * v.w;
                }
            }
            #pragma unroll
            for (int d = 0; d < HD; d++) {
                acc[d] += __shfl_xor_sync(0xffffffffu, acc[d], 1);
                acc[d] += __shfl_xor_sync(0xffffffffu, acc[d], 2);
            }
            // overwrite q slice of this head with the attention output
            #pragma unroll
            for (int dd = 0; dd < 6; dd++) {
                int d = sub * 6 + dd;
                qkv[i * QKV_STRIDE + h * HD + d] = acc[d] * rinv;
            }
            __syncwarp();
        }
    }
    __syncthreads();

    // ================= proj GEMM + residual + scatter ======================
    // o lives in qkv cols [0,192)
    for (int p = 0; p < 3; p++) {
        const int cp = p * 64;
        float acc[4][4];
        #pragma unroll
        for (int r = 0; r < 4; r++)
            #pragma unroll
            for (int c = 0; c < 4; c++) acc[r][c] = 0.f;
        for (int kh = 0; kh < 2; kh++) {
            __syncthreads();
            load_wpT(wpT, proj_w, cp, kh, t);
            __syncthreads();
            gemm_accum(qkv + r0 * QKV_STRIDE + kh * KHALF, QKV_STRIDE, wpT, c0, acc);
        }
        #pragma unroll
        for (int c = 0; c < 4; c++) {
            int col = cp + c0 + c;
            float pb = proj_b[col];
            #pragma unroll
            for (int r = 0; r < 4; r++) {
                int n = r0 + r;
                size_t g = ((size_t)col * HIMG + h0 + (n >> 3)) * WIMG + w0 + (n & 7);
                out[obase + g] = xb[g] + acc[r][c] + pb;
            }
        }
    }
}

// ---------------------------------------------------------------------------
extern "C" void kernel_launch(void* const* d_in, const int* in_sizes, int n_in,
                              void* d_out, int out_size) {
    (void)in_sizes; (void)n_in; (void)out_size;
    const float* x           = (const float*)d_in[0];
    /* d_in[1] img_alpha: mathematically a no-op (all-ones, shift=0) */
    const float* qkv_w       = (const float*)d_in[2];
    const float* q_bias      = (const float*)d_in[3];
    const float* v_bias      = (const float*)d_in[4];
    const float* logit_scale = (const float*)d_in[5];
    const float* cpb_w1      = (const float*)d_in[6];
    const float* cpb_b1      = (const float*)d_in[7];
    const float* cpb_w2      = (const float*)d_in[8];
    const float* proj_w      = (const float*)d_in[9];
    const float* proj_b      = (const float*)d_in[10];
    float* out = (float*)d_out;

    const size_t SMEM =
        (size_t)(NTOK * XS_STRIDE + NTOK * QKV_STRIDE + KHALF * WP_STRIDE) * sizeof(float);
    cudaFuncSetAttribute(win_attn_kernel,
                         cudaFuncAttributeMaxDynamicSharedMemorySize, (int)SMEM);

    bias_kernel<<<1, 256>>>(cpb_w1, cpb_b1, cpb_w2);
    win_attn_kernel<<<NWIN_TOT, 256, SMEM>>>(x, qkv_w, q_bias, v_bias,
                                             logit_scale, proj_w, proj_b, out);
}

// round 3
// speedup vs baseline: 1.0986x; 1.0986x over previous
#include <cuda_runtime.h>
#include <math.h>

#define WSZ      8
#define NH       8
#define CDIM     192
#define HD       24
#define NTOK     64
#define HIMG     256
#define WIMG     256
#define NWIN_TOT 4096

// smem strides (floats), padded for bank-conflict-free float4 access
#define XS_STRIDE  196   // 196 % 32 == 4
#define QKV_STRIDE 580   // 580 % 32 == 4
#define WP_STRIDE  68    // 68  % 32 == 4
#define KHALF      96    // K staged in 2 halves of 96

typedef unsigned long long ull;

__device__ float g_bias[NH * NTOK * NTOK];   // 128 KB, L2-resident

// ---------------- f32x2 packed helpers (FFMA2 path) ------------------------
__device__ __forceinline__ ull f2fma(ull a, ull b, ull c) {
    ull d;
    asm("fma.rn.f32x2 %0, %1, %2, %3;" : "=l"(d) : "l"(a), "l"(b), "l"(c));
    return d;
}
__device__ __forceinline__ ull f2dup(float x) {
    ull d; unsigned u = __float_as_uint(x);
    asm("mov.b64 %0, {%1, %2};" : "=l"(d) : "r"(u), "r"(u));
    return d;
}
__device__ __forceinline__ ull f2pack(float x, float y) {
    ull d; unsigned a = __float_as_uint(x), b = __float_as_uint(y);
    asm("mov.b64 %0, {%1, %2};" : "=l"(d) : "r"(a), "r"(b));
    return d;
}
__device__ __forceinline__ float2 f2unpk(ull v) {
    unsigned a, b;
    asm("mov.b64 {%0, %1}, %2;" : "=r"(a), "=r"(b) : "l"(v));
    return make_float2(__uint_as_float(a), __uint_as_float(b));
}

// ---------------------------------------------------------------------------
// Kernel A: relative-position-bias table  (225,2) -> MLP(2->512->8) -> gather
// ---------------------------------------------------------------------------
__global__ void bias_kernel(const float* __restrict__ cpb_w1,
                            const float* __restrict__ cpb_b1,
                            const float* __restrict__ cpb_w2) {
    __shared__ float s_table[225 * NH];
    int t = threadIdx.x;
    if (t < 225) {
        int a = t / 15, b = t - a * 15;
        float t0 = (float)(a - 7) * (8.0f / 7.0f);
        float t1 = (float)(b - 7) * (8.0f / 7.0f);
        const float inv_l8 = 1.0f / 3.0f;                 // 1/log2(8)
        float r0 = copysignf(log2f(fabsf(t0) + 1.0f) * inv_l8, t0);
        float r1 = copysignf(log2f(fabsf(t1) + 1.0f) * inv_l8, t1);
        float acc[NH];
        #pragma unroll
        for (int h = 0; h < NH; h++) acc[h] = 0.f;
        for (int k = 0; k < 512; k++) {
            float hv = r0 * cpb_w1[k] + r1 * cpb_w1[512 + k] + cpb_b1[k];
            hv = fmaxf(hv, 0.f);
            #pragma unroll
            for (int h = 0; h < NH; h++) acc[h] += hv * cpb_w2[k * NH + h];
        }
        #pragma unroll
        for (int h = 0; h < NH; h++)
            s_table[t * NH + h] = 16.f / (1.f + expf(-acc[h]));
    }
    __syncthreads();
    for (int id = t; id < NH * NTOK * NTOK; id += blockDim.x) {
        int h = id >> 12;
        int i = (id >> 6) & 63;
        int j = id & 63;
        int di = (i >> 3) - (j >> 3) + 7;
        int dj = (i & 7)  - (j & 7)  + 7;
        g_bias[id] = s_table[(di * 15 + dj) * NH + h];
    }
}

// ---------------------------------------------------------------------------
// GEMM helpers: 64xP panel, K staged in smem (transposed, [k][col]), 4x4 tiles
// accumulators are f32x2 pairs over column pairs -> FFMA2
// ---------------------------------------------------------------------------
__device__ __forceinline__ void load_wpT(float* wpT, const float* __restrict__ W,
                                         int cp, int kh, int t) {
    // wpT[k][c] = W[(cp+c)*CDIM + kh*KHALF + k]   (coalesced gmem reads)
    for (int idx = t; idx < 64 * KHALF; idx += 256) {
        int c = idx / KHALF;
        int k = idx - c * KHALF;
        wpT[k * WP_STRIDE + c] = W[(cp + c) * CDIM + kh * KHALF + k];
    }
}

__device__ __forceinline__ void gemm_accum2(const float* __restrict__ a_base, int lda,
                                            const float* __restrict__ wpT, int c0,
                                            ull acc2[4][2]) {
    #pragma unroll 4
    for (int k4 = 0; k4 < KHALF; k4 += 4) {
        float4 b0 = *(const float4*)(wpT + (k4 + 0) * WP_STRIDE + c0);
        float4 b1 = *(const float4*)(wpT + (k4 + 1) * WP_STRIDE + c0);
        float4 b2 = *(const float4*)(wpT + (k4 + 2) * WP_STRIDE + c0);
        float4 b3 = *(const float4*)(wpT + (k4 + 3) * WP_STRIDE + c0);
        ull b0l = f2pack(b0.x, b0.y), b0h = f2pack(b0.z, b0.w);
        ull b1l = f2pack(b1.x, b1.y), b1h = f2pack(b1.z, b1.w);
        ull b2l = f2pack(b2.x, b2.y), b2h = f2pack(b2.z, b2.w);
        ull b3l = f2pack(b3.x, b3.y), b3h = f2pack(b3.z, b3.w);
        #pragma unroll
        for (int r = 0; r < 4; r++) {
            float4 a = *(const float4*)(a_base + r * lda + k4);
            ull pa;
            pa = f2dup(a.x);
            acc2[r][0] = f2fma(pa, b0l, acc2[r][0]);
            acc2[r][1] = f2fma(pa, b0h, acc2[r][1]);
            pa = f2dup(a.y);
            acc2[r][0] = f2fma(pa, b1l, acc2[r][0]);
            acc2[r][1] = f2fma(pa, b1h, acc2[r][1]);
            pa = f2dup(a.z);
            acc2[r][0] = f2fma(pa, b2l, acc2[r][0]);
            acc2[r][1] = f2fma(pa, b2h, acc2[r][1]);
            pa = f2dup(a.w);
            acc2[r][0] = f2fma(pa, b3l, acc2[r][0]);
            acc2[r][1] = f2fma(pa, b3h, acc2[r][1]);
        }
    }
}

// ---------------------------------------------------------------------------
// Kernel B: fused window attention, one CTA per 8x8 window
// ---------------------------------------------------------------------------
__global__ void __launch_bounds__(256)
win_attn_kernel(const float* __restrict__ x,
                const float* __restrict__ qkv_w,
                const float* __restrict__ q_bias,
                const float* __restrict__ v_bias,
                const float* __restrict__ logit_scale,
                const float* __restrict__ proj_w,
                const float* __restrict__ proj_b,
                float* __restrict__ out) {
    extern __shared__ float smem[];
    float* xs  = smem;                         // [64][196]
    float* qkv = xs  + NTOK * XS_STRIDE;       // [64][580] (q|k|v cols 0..575)
    float* wpT = qkv + NTOK * QKV_STRIDE;      // [96][68] weight panel / norms
    __shared__ float s_scale[NH];

    const int t    = threadIdx.x;
    const int wi   = blockIdx.x;
    const int b    = wi >> 10;
    const int hblk = (wi >> 5) & 31;
    const int wblk = wi & 31;
    const int h0   = hblk * 8, w0 = wblk * 8;

    const float* xb = x + (size_t)b * CDIM * HIMG * WIMG;
    const size_t obase = (size_t)b * CDIM * HIMG * WIMG;

    // ---- gather window: xs[n][c] = x[b][c][h0+n/8][w0+n%8]
    for (int idx = t; idx < NTOK * CDIM; idx += 256) {
        int c = idx >> 6;
        int n = idx & 63;
        xs[n * XS_STRIDE + c] =
            xb[((size_t)c * HIMG + h0 + (n >> 3)) * WIMG + w0 + (n & 7)];
    }
    if (t < NH)
        s_scale[t] = expf(fminf(logit_scale[t], 4.60517018598809136804f)); // ln(100)
    __syncthreads();

    const int tx = t & 15, ty = t >> 4;
    const int c0 = tx * 4, r0 = ty * 4;

    // ================= QKV GEMM: qkv[64][576] = xs @ qkv_w^T + bias ========
    for (int p = 0; p < 9; p++) {
        const int cp = p * 64;
        ull acc2[4][2];
        #pragma unroll
        for (int r = 0; r < 4; r++) { acc2[r][0] = 0ull; acc2[r][1] = 0ull; }
        for (int kh = 0; kh < 2; kh++) {
            __syncthreads();                    // wpT free to overwrite
            load_wpT(wpT, qkv_w, cp, kh, t);
            __syncthreads();
            gemm_accum2(xs + r0 * XS_STRIDE + kh * KHALF, XS_STRIDE, wpT, c0, acc2);
        }
        #pragma unroll
        for (int c2 = 0; c2 < 2; c2++) {
            int col = cp + c0 + 2 * c2;
            float cb0, cb1;
            if (col < CDIM)          { cb0 = q_bias[col];            cb1 = q_bias[col + 1]; }
            else if (col < 2 * CDIM) { cb0 = 0.f;                    cb1 = 0.f; }
            else                     { cb0 = v_bias[col - 2 * CDIM]; cb1 = v_bias[col - 2 * CDIM + 1]; }
            #pragma unroll
            for (int r = 0; r < 4; r++) {
                float2 v = f2unpk(acc2[r][c2]);
                qkv[(r0 + r) * QKV_STRIDE + col]     = v.x + cb0;
                qkv[(r0 + r) * QKV_STRIDE + col + 1] = v.y + cb1;
            }
        }
    }
    __syncthreads();

    // ================= q/k row reciprocal norms ============================
    float* s_rq = wpT;         // [64][8]
    float* s_rk = wpT + 512;   // [64][8]
    for (int id = t; id < 1024; id += 256) {
        int qk = id >> 9;
        int n  = (id >> 3) & 63;
        int h  = id & 7;
        const float* p = qkv + n * QKV_STRIDE + qk * CDIM + h * HD;
        float s = 0.f;
        #pragma unroll
        for (int d4 = 0; d4 < 6; d4++) {
            float4 v = *(const float4*)(p + d4 * 4);
            s += v.x * v.x + v.y * v.y + v.z * v.z + v.w * v.w;
        }
        float r = 1.f / fmaxf(sqrtf(s), 1e-12f);
        (qk ? s_rk : s_rq)[n * 8 + h] = r;
    }
    __syncthreads();

    // ================= attention: per head, all in registers ================
    // thread t: row i = t>>2, covers keys j = sub + 4*jj (sub = t&3)
    {
        const int i   = t >> 2;
        const int sub = t & 3;
        const float* qrow = qkv + i * QKV_STRIDE;

        for (int h = 0; h < NH; h++) {
            const float* qh = qrow + h * HD;
            // q row as 12 packed f32x2 pairs (pairs along d)
            ull qp[12];
            #pragma unroll
            for (int d4 = 0; d4 < 6; d4++) {
                float4 q = *(const float4*)(qh + d4 * 4);
                qp[d4 * 2 + 0] = f2pack(q.x, q.y);
                qp[d4 * 2 + 1] = f2pack(q.z, q.w);
            }
            const float coef = s_rq[i * 8 + h] * s_scale[h];
            const float* bb  = g_bias + h * 4096 + i * 64;

            float e[16];
            float m = -1e30f;
            #pragma unroll
            for (int jj = 0; jj < 16; jj++) {
                int j = sub + 4 * jj;
                const float* kr = qkv + j * QKV_STRIDE + CDIM + h * HD;
                ull s2a = 0ull, s2b = 0ull;
                #pragma unroll
                for (int d4 = 0; d4 < 6; d4++) {
                    float4 k = *(const float4*)(kr + d4 * 4);
                    s2a = f2fma(qp[d4 * 2 + 0], f2pack(k.x, k.y), s2a);
                    s2b = f2fma(qp[d4 * 2 + 1], f2pack(k.z, k.w), s2b);
                }
                float2 da = f2unpk(s2a);
                float2 db = f2unpk(s2b);
                float dot = (da.x + da.y) + (db.x + db.y);
                float lg = dot * coef * s_rk[j * 8 + h] + __ldg(bb + j);
                e[jj] = lg;
                m = fmaxf(m, lg);
            }
            m = fmaxf(m, __shfl_xor_sync(0xffffffffu, m, 1));
            m = fmaxf(m, __shfl_xor_sync(0xffffffffu, m, 2));
            float sum = 0.f;
            #pragma unroll
            for (int jj = 0; jj < 16; jj++) {
                e[jj] = __expf(e[jj] - m);
                sum += e[jj];
            }
            sum += __shfl_xor_sync(0xffffffffu, sum, 1);
            sum += __shfl_xor_sync(0xffffffffu, sum, 2);
            const float rinv = 1.f / sum;

            // PV: accumulate over keys, d packed in pairs (12 f32x2 accumulators)
            ull acc2[12];
            #pragma unroll
            for (int dp = 0; dp < 12; dp++) acc2[dp] = 0ull;
            #pragma unroll
            for (int jj = 0; jj < 16; jj++) {
                int j = sub + 4 * jj;
                const float* vr = qkv + j * QKV_STRIDE + 2 * CDIM + h * HD;
                ull ep = f2dup(e[jj]);
                #pragma unroll
                for (int d4 = 0; d4 < 6; d4++) {
                    float4 v = *(const float4*)(vr + d4 * 4);
                    acc2[d4 * 2 + 0] = f2fma(ep, f2pack(v.x, v.y), acc2[d4 * 2 + 0]);
                    acc2[d4 * 2 + 1] = f2fma(ep, f2pack(v.z, v.w), acc2[d4 * 2 + 1]);
                }
            }
            float acc[HD];
            #pragma unroll
            for (int dp = 0; dp < 12; dp++) {
                float2 v = f2unpk(acc2[dp]);
                acc[dp * 2 + 0] = v.x;
                acc[dp * 2 + 1] = v.y;
            }
            #pragma unroll
            for (int d = 0; d < HD; d++) {
                acc[d] += __shfl_xor_sync(0xffffffffu, acc[d], 1);
                acc[d] += __shfl_xor_sync(0xffffffffu, acc[d], 2);
            }
            // overwrite q slice of this head with the attention output
            #pragma unroll
            for (int dd = 0; dd < 6; dd++) {
                int d = sub * 6 + dd;
                qkv[i * QKV_STRIDE + h * HD + d] = acc[d] * rinv;
            }
            __syncwarp();
        }
    }
    __syncthreads();

    // ================= proj GEMM + residual + scatter ======================
    // o lives in qkv cols [0,192)
    for (int p = 0; p < 3; p++) {
        const int cp = p * 64;
        ull acc2[4][2];
        #pragma unroll
        for (int r = 0; r < 4; r++) { acc2[r][0] = 0ull; acc2[r][1] = 0ull; }
        for (int kh = 0; kh < 2; kh++) {
            __syncthreads();
            load_wpT(wpT, proj_w, cp, kh, t);
            __syncthreads();
            gemm_accum2(qkv + r0 * QKV_STRIDE + kh * KHALF, QKV_STRIDE, wpT, c0, acc2);
        }
        #pragma unroll
        for (int c2 = 0; c2 < 2; c2++) {
            int col = cp + c0 + 2 * c2;
            float pb0 = proj_b[col];
            float pb1 = proj_b[col + 1];
            #pragma unroll
            for (int r = 0; r < 4; r++) {
                int n = r0 + r;
                float2 v = f2unpk(acc2[r][c2]);
                size_t g0 = ((size_t)col * HIMG + h0 + (n >> 3)) * WIMG + w0 + (n & 7);
                size_t g1 = g0 + (size_t)HIMG * WIMG;
                out[obase + g0] = xb[g0] + v.x + pb0;
                out[obase + g1] = xb[g1] + v.y + pb1;
            }
        }
    }
}

// ---------------------------------------------------------------------------
extern "C" void kernel_launch(void* const* d_in, const int* in_sizes, int n_in,
                              void* d_out, int out_size) {
    (void)in_sizes; (void)n_in; (void)out_size;
    const float* x           = (const float*)d_in[0];
    /* d_in[1] img_alpha: mathematically a no-op (all-ones, shift=0) */
    const float* qkv_w       = (const float*)d_in[2];
    const float* q_bias      = (const float*)d_in[3];
    const float* v_bias      = (const float*)d_in[4];
    const float* logit_scale = (const float*)d_in[5];
    const float* cpb_w1      = (const float*)d_in[6];
    const float* cpb_b1      = (const float*)d_in[7];
    const float* cpb_w2      = (const float*)d_in[8];
    const float* proj_w      = (const float*)d_in[9];
    const float* proj_b      = (const float*)d_in[10];
    float* out = (float*)d_out;

    const size_t SMEM =
        (size_t)(NTOK * XS_STRIDE + NTOK * QKV_STRIDE + KHALF * WP_STRIDE) * sizeof(float);
    cudaFuncSetAttribute(win_attn_kernel,
                         cudaFuncAttributeMaxDynamicSharedMemorySize, (int)SMEM);

    bias_kernel<<<1, 256>>>(cpb_w1, cpb_b1, cpb_w2);
    win_attn_kernel<<<NWIN_TOT, 256, SMEM>>>(x, qkv_w, q_bias, v_bias,
                                             logit_scale, proj_w, proj_b, out);
}